// round 2
// baseline (speedup 1.0000x reference)
#include <cuda_runtime.h>
#include <math.h>

// Problem constants (match reference)
#define NN   100000
#define EE   3200000
#define FIN  512
#define HID  64
#define CC   16

// ---------------- device scratch (no allocs allowed) ----------------
__device__ float g_h1[NN * HID];    // x @ W1^T
__device__ float g_agg1[NN * HID];  // edge-aggregated h1
__device__ float g_h2[NN * CC];     // relu(...) @ W2^T
__device__ float g_deg[NN];
__device__ float g_dinv[NN];

// vectorized global reduction (sm_90+): 1 instruction, 16 bytes
__device__ __forceinline__ void red_add_v4(float* dst, float x, float y, float z, float w) {
    asm volatile("red.global.add.v4.f32 [%0], {%1, %2, %3, %4};"
                 :: "l"(dst), "f"(x), "f"(y), "f"(z), "f"(w) : "memory");
}

// ---------------- K0: init ----------------
// zero g_agg1 (N*64), zero d_out (N*16), deg = 1.0 (self loop weight)
__global__ void init_kernel(float* __restrict__ dout) {
    int i = blockIdx.x * blockDim.x + threadIdx.x;   // 0 .. N*HID-1
    g_agg1[i] = 0.0f;
    if (i < NN * CC) dout[i] = 0.0f;
    if (i < NN)      g_deg[i] = 1.0f;
}

// ---------------- K1: GEMM1  h1 = x @ W1^T ----------------
// x:[N,512], W1:[64,512] -> h1:[N,64]
// BM=128, BN=64, BK=8, 256 threads, each thread 8x4 micro-tile.
__global__ __launch_bounds__(256) void gemm1_kernel(const float* __restrict__ X,
                                                    const float* __restrict__ W) {
    __shared__ float As[8][132];   // [k][m], padded
    __shared__ float Bs[8][68];    // [k][n], padded

    const int tid = threadIdx.x;
    const int block_row = blockIdx.x * 128;
    const int tx = tid & 15;       // n group
    const int ty = tid >> 4;       // m group

    const int a_r = tid >> 1;          // 0..127
    const int a_k = (tid & 1) * 4;
    const int b_n = tid >> 1;          // 0..63 for tid<128
    const int b_k = (tid & 1) * 4;

    float acc[8][4];
#pragma unroll
    for (int i = 0; i < 8; i++)
#pragma unroll
        for (int j = 0; j < 4; j++) acc[i][j] = 0.0f;

    for (int k0 = 0; k0 < FIN; k0 += 8) {
        // A tile
        int gr = block_row + a_r;
        float4 av = make_float4(0.f, 0.f, 0.f, 0.f);
        if (gr < NN) av = *(const float4*)&X[(size_t)gr * FIN + k0 + a_k];
        As[a_k + 0][a_r] = av.x;
        As[a_k + 1][a_r] = av.y;
        As[a_k + 2][a_r] = av.z;
        As[a_k + 3][a_r] = av.w;
        // B tile
        if (tid < 128) {
            float4 bv = *(const float4*)&W[(size_t)b_n * FIN + k0 + b_k];
            Bs[b_k + 0][b_n] = bv.x;
            Bs[b_k + 1][b_n] = bv.y;
            Bs[b_k + 2][b_n] = bv.z;
            Bs[b_k + 3][b_n] = bv.w;
        }
        __syncthreads();

#pragma unroll
        for (int kk = 0; kk < 8; kk++) {
            float4 a0 = *(const float4*)&As[kk][ty * 8];
            float4 a1 = *(const float4*)&As[kk][ty * 8 + 4];
            float4 b0 = *(const float4*)&Bs[kk][tx * 4];
            float a[8] = {a0.x, a0.y, a0.z, a0.w, a1.x, a1.y, a1.z, a1.w};
            float b[4] = {b0.x, b0.y, b0.z, b0.w};
#pragma unroll
            for (int i = 0; i < 8; i++)
#pragma unroll
                for (int j = 0; j < 4; j++)
                    acc[i][j] = fmaf(a[i], b[j], acc[i][j]);
        }
        __syncthreads();
    }

#pragma unroll
    for (int i = 0; i < 8; i++) {
        int gr = block_row + ty * 8 + i;
        if (gr < NN) {
            float4 o = make_float4(acc[i][0], acc[i][1], acc[i][2], acc[i][3]);
            *(float4*)&g_h1[(size_t)gr * HID + tx * 4] = o;
        }
    }
}

// ---------------- K2: degree ----------------
__global__ void deg_kernel(const int* __restrict__ col, const float* __restrict__ ea) {
    int e = blockIdx.x * blockDim.x + threadIdx.x;   // 0..E-1
    atomicAdd(&g_deg[col[e]], ea[e]);
}

// ---------------- K3: dinv ----------------
__global__ void dinv_kernel() {
    int i = blockIdx.x * blockDim.x + threadIdx.x;
    if (i < NN) {
        float d = g_deg[i];
        g_dinv[i] = (d > 0.0f) ? rsqrtf(d) : 0.0f;
    }
}

// ---------------- K4: layer-1 edge aggregation ----------------
// 16 threads per edge, one v4 reduction each (64 feats). agg1[col] += h1[row]*norm
__global__ void agg1_kernel(const int* __restrict__ row, const int* __restrict__ col,
                            const float* __restrict__ ea) {
    int i = blockIdx.x * blockDim.x + threadIdx.x;   // 0 .. E*16-1
    int e   = i >> 4;
    int seg = (i & 15) << 2;                          // 0,4,...,60
    int r = row[e];
    int c = col[e];
    float nrm = g_dinv[r] * ea[e] * g_dinv[c];
    float4 v = *(const float4*)&g_h1[(size_t)r * HID + seg];
    float* dst = &g_agg1[(size_t)c * HID + seg];
    red_add_v4(dst, v.x * nrm, v.y * nrm, v.z * nrm, v.w * nrm);
}

// ---------------- K5: fused self-loop + bias + ReLU + GEMM2 ----------------
// h2 = relu(agg1 + h1*dinv^2 + b1) @ W2^T     (W2:[16,64])
// block = 256 threads = 16 rows x 16 out-cols
__global__ __launch_bounds__(256) void gemm2relu_kernel(const float* __restrict__ b1,
                                                        const float* __restrict__ W2) {
    __shared__ float R[16][65];     // [row][k]
    __shared__ float W2s[64][17];   // [k][n]

    const int tid = threadIdx.x;
    const int rowblk = blockIdx.x * 16;

    // stage W2 transposed
    {
        int n  = tid >> 4;            // 0..15
        int k4 = (tid & 15) << 2;     // 0..60
        float4 w = *(const float4*)&W2[(size_t)n * HID + k4];
        W2s[k4 + 0][n] = w.x;
        W2s[k4 + 1][n] = w.y;
        W2s[k4 + 2][n] = w.z;
        W2s[k4 + 3][n] = w.w;
    }
    // stage relu(agg1 + self + b1)
    {
        int r  = tid >> 4;            // 0..15
        int k4 = (tid & 15) << 2;
        int grow = rowblk + r;
        float di = g_dinv[grow];
        float d2 = di * di;
        float4 a = *(const float4*)&g_agg1[(size_t)grow * HID + k4];
        float4 s = *(const float4*)&g_h1[(size_t)grow * HID + k4];
        float4 bb = *(const float4*)&b1[k4];
        R[r][k4 + 0] = fmaxf(a.x + s.x * d2 + bb.x, 0.0f);
        R[r][k4 + 1] = fmaxf(a.y + s.y * d2 + bb.y, 0.0f);
        R[r][k4 + 2] = fmaxf(a.z + s.z * d2 + bb.z, 0.0f);
        R[r][k4 + 3] = fmaxf(a.w + s.w * d2 + bb.w, 0.0f);
    }
    __syncthreads();

    int r = tid >> 4;
    int n = tid & 15;
    float acc = 0.0f;
#pragma unroll
    for (int k = 0; k < HID; k++) acc = fmaf(R[r][k], W2s[k][n], acc);
    g_h2[(size_t)(rowblk + r) * CC + n] = acc;
}

// ---------------- K6: layer-2 edge aggregation ----------------
// 4 threads per edge, one v4 reduction each (16 feats). dout[col] += h2[row]*norm
__global__ void agg2_kernel(const int* __restrict__ row, const int* __restrict__ col,
                            const float* __restrict__ ea, float* __restrict__ dout) {
    int i = blockIdx.x * blockDim.x + threadIdx.x;   // 0 .. E*4-1
    int e   = i >> 2;
    int seg = (i & 3) << 2;                           // 0,4,8,12
    int r = row[e];
    int c = col[e];
    float nrm = g_dinv[r] * ea[e] * g_dinv[c];
    float4 v = *(const float4*)&g_h2[(size_t)r * CC + seg];
    float* dst = &dout[(size_t)c * CC + seg];
    red_add_v4(dst, v.x * nrm, v.y * nrm, v.z * nrm, v.w * nrm);
}

// ---------------- K7: self-loop + b2 + log_softmax (in place on d_out) ----------------
__global__ void lsm_kernel(float* __restrict__ dout, const float* __restrict__ b2) {
    int gi = blockIdx.x * blockDim.x + threadIdx.x;   // 0 .. N*16-1
    int r = gi >> 4;
    int n = gi & 15;
    float di = g_dinv[r];
    float v = dout[gi] + g_h2[gi] * (di * di) + b2[n];

    // reductions within the 16-lane group (xor<16 stays in group)
    float m = v;
#pragma unroll
    for (int k = 8; k >= 1; k >>= 1)
        m = fmaxf(m, __shfl_xor_sync(0xFFFFFFFFu, m, k));
    float s = __expf(v - m);
#pragma unroll
    for (int k = 8; k >= 1; k >>= 1)
        s += __shfl_xor_sync(0xFFFFFFFFu, s, k);
    dout[gi] = (v - m) - __logf(s);
}

// ---------------- launch ----------------
extern "C" void kernel_launch(void* const* d_in, const int* in_sizes, int n_in,
                              void* d_out, int out_size) {
    const float* x  = (const float*)d_in[0];
    const int*   ei = (const int*)d_in[1];
    const float* ea = (const float*)d_in[2];
    const float* W1 = (const float*)d_in[3];
    const float* b1 = (const float*)d_in[4];
    const float* W2 = (const float*)d_in[5];
    const float* b2 = (const float*)d_in[6];
    float* dout = (float*)d_out;

    const int* row = ei;        // edge_index[0]
    const int* col = ei + EE;   // edge_index[1]

    init_kernel<<<(NN * HID) / 256, 256>>>(dout);
    gemm1_kernel<<<(NN + 127) / 128, 256>>>(x, W1);
    deg_kernel<<<EE / 256, 256>>>(col, ea);
    dinv_kernel<<<(NN + 255) / 256, 256>>>();
    agg1_kernel<<<(EE * 16) / 256, 256>>>(row, col, ea);
    gemm2relu_kernel<<<NN / 16, 256>>>(b1, W2);
    agg2_kernel<<<(EE * 4) / 256, 256>>>(row, col, ea, dout);
    lsm_kernel<<<(NN * CC) / 256, 256>>>(dout, b2);
}

// round 3
// speedup vs baseline: 1.0918x; 1.0918x over previous
#include <cuda_runtime.h>
#include <math.h>
#include <stdint.h>

// Problem constants (match reference)
#define NN   100000
#define EE   3200000
#define FIN  512
#define HID  64
#define CC   16

// ---------------- device scratch (no allocs allowed) ----------------
__device__ float g_h1[NN * HID];    // x @ W1^T
__device__ float g_agg1[NN * HID];  // edge-aggregated h1
__device__ float g_h2[NN * CC];     // relu(...) @ W2^T
__device__ float g_deg[NN];
__device__ float g_dinv[NN];

// vectorized global reduction (sm_90+): 1 instruction, 16 bytes
__device__ __forceinline__ void red_add_v4(float* dst, float x, float y, float z, float w) {
    asm volatile("red.global.add.v4.f32 [%0], {%1, %2, %3, %4};"
                 :: "l"(dst), "f"(x), "f"(y), "f"(z), "f"(w) : "memory");
}

__device__ __forceinline__ uint32_t cvt_tf32(float f) {
    uint32_t u;
    asm("cvt.rna.tf32.f32 %0, %1;" : "=r"(u) : "f"(f));
    return u;
}

__device__ __forceinline__ void mma_tf32(float* c, const uint32_t* a, const uint32_t* b) {
    asm volatile(
        "mma.sync.aligned.m16n8k8.row.col.f32.tf32.tf32.f32 "
        "{%0,%1,%2,%3}, {%4,%5,%6,%7}, {%8,%9}, {%0,%1,%2,%3};"
        : "+f"(c[0]), "+f"(c[1]), "+f"(c[2]), "+f"(c[3])
        : "r"(a[0]), "r"(a[1]), "r"(a[2]), "r"(a[3]), "r"(b[0]), "r"(b[1]));
}

__device__ __forceinline__ void cp_async16(uint32_t smem_dst, const void* gsrc, int src_bytes) {
    asm volatile("cp.async.cg.shared.global [%0], [%1], 16, %2;"
                 :: "r"(smem_dst), "l"(gsrc), "r"(src_bytes));
}

// ---------------- K0: init ----------------
__global__ void init_kernel(float* __restrict__ dout) {
    int i = blockIdx.x * blockDim.x + threadIdx.x;   // 0 .. N*HID-1
    g_agg1[i] = 0.0f;
    if (i < NN * CC) dout[i] = 0.0f;
    if (i < NN)      g_deg[i] = 1.0f;
}

// ---------------- K1: GEMM1  h1 = x @ W1^T  (3xTF32 tensor core) ----------------
// X:[N,512] row-major, W:[64,512] row-major. BM=128, BN=64, BK=16.
// 8 warps, each computes a 16x64 strip via m16n8k8 tf32 mma, 3-term split for fp32 accuracy.
#define BM  128
#define BKg 16
#define AST 20
#define BST 20

__global__ __launch_bounds__(256) void gemm1_tc(const float* __restrict__ X,
                                                const float* __restrict__ W) {
    __shared__ float As[2][BM][AST];
    __shared__ float Bs[2][64][BST];

    const int tid = threadIdx.x;
    const int warp = tid >> 5;
    const int lane = tid & 31;
    const int blockRow = blockIdx.x * BM;

    // load mapping
    const int a_row = tid >> 2;           // 0..63 (and +64)
    const int a_c  = (tid & 3) * 4;       // 0,4,8,12
    const int b_row = tid >> 2;           // 0..63
    const int b_c  = (tid & 3) * 4;

    const int tig = lane & 3;
    const int g   = lane >> 2;
    const int r0  = (warp << 4) + g;

    float acc[8][4];
#pragma unroll
    for (int j = 0; j < 8; j++)
#pragma unroll
        for (int q = 0; q < 4; q++) acc[j][q] = 0.0f;

    // ---- prologue: stage 0 ----
    {
        int gr0 = blockRow + a_row;
        int gr1 = blockRow + a_row + 64;
        cp_async16((uint32_t)__cvta_generic_to_shared(&As[0][a_row][a_c]),
                   &X[(size_t)gr0 * FIN + a_c], gr0 < NN ? 16 : 0);
        cp_async16((uint32_t)__cvta_generic_to_shared(&As[0][a_row + 64][a_c]),
                   &X[(size_t)gr1 * FIN + a_c], gr1 < NN ? 16 : 0);
        cp_async16((uint32_t)__cvta_generic_to_shared(&Bs[0][b_row][b_c]),
                   &W[(size_t)b_row * FIN + b_c], 16);
        asm volatile("cp.async.commit_group;");
    }

#pragma unroll 1
    for (int kt = 0; kt < FIN / BKg; kt++) {
        const int st = kt & 1;
        if (kt + 1 < FIN / BKg) {
            const int ns = (kt + 1) & 1;
            const int k0 = (kt + 1) * BKg;
            int gr0 = blockRow + a_row;
            int gr1 = blockRow + a_row + 64;
            cp_async16((uint32_t)__cvta_generic_to_shared(&As[ns][a_row][a_c]),
                       &X[(size_t)gr0 * FIN + k0 + a_c], gr0 < NN ? 16 : 0);
            cp_async16((uint32_t)__cvta_generic_to_shared(&As[ns][a_row + 64][a_c]),
                       &X[(size_t)gr1 * FIN + k0 + a_c], gr1 < NN ? 16 : 0);
            cp_async16((uint32_t)__cvta_generic_to_shared(&Bs[ns][b_row][b_c]),
                       &W[(size_t)b_row * FIN + k0 + b_c], 16);
            asm volatile("cp.async.commit_group;");
            asm volatile("cp.async.wait_group 1;");
        } else {
            asm volatile("cp.async.wait_group 0;");
        }
        __syncthreads();

#pragma unroll
        for (int kk = 0; kk < BKg; kk += 8) {
            float af0 = As[st][r0    ][kk + tig];
            float af1 = As[st][r0 + 8][kk + tig];
            float af2 = As[st][r0    ][kk + tig + 4];
            float af3 = As[st][r0 + 8][kk + tig + 4];
            uint32_t ah[4], al[4];
            ah[0] = cvt_tf32(af0); al[0] = cvt_tf32(af0 - __uint_as_float(ah[0]));
            ah[1] = cvt_tf32(af1); al[1] = cvt_tf32(af1 - __uint_as_float(ah[1]));
            ah[2] = cvt_tf32(af2); al[2] = cvt_tf32(af2 - __uint_as_float(ah[2]));
            ah[3] = cvt_tf32(af3); al[3] = cvt_tf32(af3 - __uint_as_float(ah[3]));
#pragma unroll
            for (int nt = 0; nt < 8; nt++) {
                float bf0 = Bs[st][nt * 8 + g][kk + tig];
                float bf1 = Bs[st][nt * 8 + g][kk + tig + 4];
                uint32_t bh[2], bl[2];
                bh[0] = cvt_tf32(bf0); bl[0] = cvt_tf32(bf0 - __uint_as_float(bh[0]));
                bh[1] = cvt_tf32(bf1); bl[1] = cvt_tf32(bf1 - __uint_as_float(bh[1]));
                mma_tf32(acc[nt], ah, bh);   // hi*hi
                mma_tf32(acc[nt], al, bh);   // lo*hi
                mma_tf32(acc[nt], ah, bl);   // hi*lo
            }
        }
        __syncthreads();
    }

    // store: c0,c1 -> (r0, 2tig..+1), c2,c3 -> (r0+8, ...)
    int grA = blockRow + r0;
    int grB = grA + 8;
#pragma unroll
    for (int nt = 0; nt < 8; nt++) {
        int ncol = nt * 8 + 2 * tig;
        if (grA < NN) {
            float2 v = make_float2(acc[nt][0], acc[nt][1]);
            *(float2*)&g_h1[(size_t)grA * HID + ncol] = v;
        }
        if (grB < NN) {
            float2 v = make_float2(acc[nt][2], acc[nt][3]);
            *(float2*)&g_h1[(size_t)grB * HID + ncol] = v;
        }
    }
}

// ---------------- K2: degree ----------------
__global__ void deg_kernel(const int* __restrict__ col, const float* __restrict__ ea) {
    int e = blockIdx.x * blockDim.x + threadIdx.x;   // 0..E-1
    atomicAdd(&g_deg[col[e]], ea[e]);
}

// ---------------- K3: dinv ----------------
__global__ void dinv_kernel() {
    int i = blockIdx.x * blockDim.x + threadIdx.x;
    if (i < NN) {
        float d = g_deg[i];
        g_dinv[i] = (d > 0.0f) ? rsqrtf(d) : 0.0f;
    }
}

// ---------------- K4: layer-1 edge aggregation ----------------
// 16 lanes per edge; leader lane loads metadata, shfl-broadcasts.
__global__ void agg1_kernel(const int* __restrict__ row, const int* __restrict__ col,
                            const float* __restrict__ ea) {
    int i = blockIdx.x * blockDim.x + threadIdx.x;   // 0 .. E*16-1
    int e   = i >> 4;
    int seg = (i & 15) << 2;                          // 0,4,...,60
    int lane = threadIdx.x & 31;
    int r = 0, c = 0; float nrm = 0.0f;
    if ((lane & 15) == 0) {
        r = row[e];
        c = col[e];
        nrm = g_dinv[r] * ea[e] * g_dinv[c];
    }
    int src = lane & 16;
    r   = __shfl_sync(0xFFFFFFFFu, r, src);
    c   = __shfl_sync(0xFFFFFFFFu, c, src);
    nrm = __shfl_sync(0xFFFFFFFFu, nrm, src);
    float4 v = *(const float4*)&g_h1[(size_t)r * HID + seg];
    float* dst = &g_agg1[(size_t)c * HID + seg];
    red_add_v4(dst, v.x * nrm, v.y * nrm, v.z * nrm, v.w * nrm);
}

// ---------------- K5: fused self-loop + bias + ReLU + GEMM2 ----------------
__global__ __launch_bounds__(256) void gemm2relu_kernel(const float* __restrict__ b1,
                                                        const float* __restrict__ W2) {
    __shared__ float R[16][65];     // [row][k]
    __shared__ float W2s[64][17];   // [k][n]

    const int tid = threadIdx.x;
    const int rowblk = blockIdx.x * 16;

    {
        int n  = tid >> 4;            // 0..15
        int k4 = (tid & 15) << 2;     // 0..60
        float4 w = *(const float4*)&W2[(size_t)n * HID + k4];
        W2s[k4 + 0][n] = w.x;
        W2s[k4 + 1][n] = w.y;
        W2s[k4 + 2][n] = w.z;
        W2s[k4 + 3][n] = w.w;
    }
    {
        int r  = tid >> 4;            // 0..15
        int k4 = (tid & 15) << 2;
        int grow = rowblk + r;
        float di = g_dinv[grow];
        float d2 = di * di;
        float4 a = *(const float4*)&g_agg1[(size_t)grow * HID + k4];
        float4 s = *(const float4*)&g_h1[(size_t)grow * HID + k4];
        float4 bb = *(const float4*)&b1[k4];
        R[r][k4 + 0] = fmaxf(a.x + s.x * d2 + bb.x, 0.0f);
        R[r][k4 + 1] = fmaxf(a.y + s.y * d2 + bb.y, 0.0f);
        R[r][k4 + 2] = fmaxf(a.z + s.z * d2 + bb.z, 0.0f);
        R[r][k4 + 3] = fmaxf(a.w + s.w * d2 + bb.w, 0.0f);
    }
    __syncthreads();

    int r = tid >> 4;
    int n = tid & 15;
    float acc = 0.0f;
#pragma unroll
    for (int k = 0; k < HID; k++) acc = fmaf(R[r][k], W2s[k][n], acc);
    g_h2[(size_t)(rowblk + r) * CC + n] = acc;
}

// ---------------- K6: layer-2 edge aggregation ----------------
// 4 lanes per edge; leader lane loads metadata, shfl-broadcasts.
__global__ void agg2_kernel(const int* __restrict__ row, const int* __restrict__ col,
                            const float* __restrict__ ea, float* __restrict__ dout) {
    int i = blockIdx.x * blockDim.x + threadIdx.x;   // 0 .. E*4-1
    int e   = i >> 2;
    int seg = (i & 3) << 2;                           // 0,4,8,12
    int lane = threadIdx.x & 31;
    int r = 0, c = 0; float nrm = 0.0f;
    if ((lane & 3) == 0) {
        r = row[e];
        c = col[e];
        nrm = g_dinv[r] * ea[e] * g_dinv[c];
    }
    int src = lane & 28;
    r   = __shfl_sync(0xFFFFFFFFu, r, src);
    c   = __shfl_sync(0xFFFFFFFFu, c, src);
    nrm = __shfl_sync(0xFFFFFFFFu, nrm, src);
    float4 v = *(const float4*)&g_h2[(size_t)r * CC + seg];
    float* dst = &dout[(size_t)c * CC + seg];
    red_add_v4(dst, v.x * nrm, v.y * nrm, v.z * nrm, v.w * nrm);
}

// ---------------- K7: self-loop + b2 + log_softmax ----------------
__global__ void lsm_kernel(float* __restrict__ dout, const float* __restrict__ b2) {
    int gi = blockIdx.x * blockDim.x + threadIdx.x;   // 0 .. N*16-1
    int r = gi >> 4;
    int n = gi & 15;
    float di = g_dinv[r];
    float v = dout[gi] + g_h2[gi] * (di * di) + b2[n];

    float m = v;
#pragma unroll
    for (int k = 8; k >= 1; k >>= 1)
        m = fmaxf(m, __shfl_xor_sync(0xFFFFFFFFu, m, k));
    float s = __expf(v - m);
#pragma unroll
    for (int k = 8; k >= 1; k >>= 1)
        s += __shfl_xor_sync(0xFFFFFFFFu, s, k);
    dout[gi] = (v - m) - __logf(s);
}

// ---------------- launch ----------------
extern "C" void kernel_launch(void* const* d_in, const int* in_sizes, int n_in,
                              void* d_out, int out_size) {
    const float* x  = (const float*)d_in[0];
    const int*   ei = (const int*)d_in[1];
    const float* ea = (const float*)d_in[2];
    const float* W1 = (const float*)d_in[3];
    const float* b1 = (const float*)d_in[4];
    const float* W2 = (const float*)d_in[5];
    const float* b2 = (const float*)d_in[6];
    float* dout = (float*)d_out;

    const int* row = ei;        // edge_index[0]
    const int* col = ei + EE;   // edge_index[1]

    init_kernel<<<(NN * HID) / 256, 256>>>(dout);
    gemm1_tc<<<(NN + BM - 1) / BM, 256>>>(x, W1);
    deg_kernel<<<EE / 256, 256>>>(col, ea);
    dinv_kernel<<<(NN + 255) / 256, 256>>>();
    agg1_kernel<<<(EE * 16) / 256, 256>>>(row, col, ea);
    gemm2relu_kernel<<<NN / 16, 256>>>(b1, W2);
    agg2_kernel<<<(EE * 4) / 256, 256>>>(row, col, ea, dout);
    lsm_kernel<<<(NN * CC) / 256, 256>>>(dout, b2);
}

// round 5
// speedup vs baseline: 1.3821x; 1.2658x over previous
#include <cuda_runtime.h>
#include <math.h>
#include <stdint.h>

// Problem constants (match reference)
#define NN   100000
#define EE   3200000
#define FIN  512
#define HID  64
#define CC   16

#define SCAN_B   1024
#define NB       ((NN + SCAN_B - 1) / SCAN_B)   // 98

// ---------------- device scratch (no allocs allowed) ----------------
__device__ float g_h1s[NN * HID];   // (x @ W1^T) * dinv[row]
__device__ float g_rel[NN * HID];   // relu(layer1 out)
__device__ float g_zs[NN * CC];     // (rel @ W2^T) * dinv[row]
__device__ float g_deg[NN];
__device__ float g_dinv[NN];
__device__ int   g_cnt[NN];
__device__ int   g_cur[NN];
__device__ int   g_off[NN + 1];
__device__ int   g_bsum[NB];
__device__ int2  g_epack[EE];       // {src row, ew bits} sorted by dst

__device__ __forceinline__ uint32_t cvt_tf32(float f) {
    uint32_t u;
    asm("cvt.rna.tf32.f32 %0, %1;" : "=r"(u) : "f"(f));
    return u;
}

__device__ __forceinline__ void mma_tf32(float* c, const uint32_t* a, const uint32_t* b) {
    asm volatile(
        "mma.sync.aligned.m16n8k8.row.col.f32.tf32.tf32.f32 "
        "{%0,%1,%2,%3}, {%4,%5,%6,%7}, {%8,%9}, {%0,%1,%2,%3};"
        : "+f"(c[0]), "+f"(c[1]), "+f"(c[2]), "+f"(c[3])
        : "r"(a[0]), "r"(a[1]), "r"(a[2]), "r"(a[3]), "r"(b[0]), "r"(b[1]));
}

__device__ __forceinline__ void cp_async16(uint32_t smem_dst, const void* gsrc, int src_bytes) {
    asm volatile("cp.async.cg.shared.global [%0], [%1], 16, %2;"
                 :: "r"(smem_dst), "l"(gsrc), "r"(src_bytes));
}

// ---------------- K0: init (cnt=0, cur=0, deg=1) ----------------
__global__ void init_kernel() {
    int i = blockIdx.x * blockDim.x + threadIdx.x;
    if (i < NN) {
        g_cnt[i] = 0;
        g_cur[i] = 0;
        g_deg[i] = 1.0f;   // self-loop weight
    }
}

// ---------------- K1: histogram + weighted degree ----------------
__global__ void hist_kernel(const int* __restrict__ col, const float* __restrict__ ea) {
    int e = blockIdx.x * blockDim.x + threadIdx.x;   // 0..E-1
    int c = col[e];
    atomicAdd(&g_cnt[c], 1);
    atomicAdd(&g_deg[c], ea[e]);
}

// ---------------- K2: scan part A (per-block exclusive scan) ----------------
__global__ __launch_bounds__(SCAN_B) void scanA_kernel() {
    __shared__ int s[SCAN_B];
    int tid = threadIdx.x;
    int i = blockIdx.x * SCAN_B + tid;
    int v = (i < NN) ? g_cnt[i] : 0;
    s[tid] = v;
    __syncthreads();
#pragma unroll
    for (int d = 1; d < SCAN_B; d <<= 1) {
        int t = (tid >= d) ? s[tid - d] : 0;
        __syncthreads();
        s[tid] += t;
        __syncthreads();
    }
    if (i <= NN) g_off[i] = s[tid] - v;   // exclusive
    if (tid == SCAN_B - 1) g_bsum[blockIdx.x] = s[tid];
}

// ---------------- K3: scan part B (scan the 98 block sums) ----------------
__global__ void scanB_kernel() {
    if (threadIdx.x == 0) {
        int acc = 0;
#pragma unroll 1
        for (int b = 0; b < NB; b++) {
            int t = g_bsum[b];
            g_bsum[b] = acc;
            acc += t;
        }
    }
}

// ---------------- K4: scan part C (add block offsets) + dinv ----------------
__global__ __launch_bounds__(SCAN_B) void scanC_kernel() {
    int i = blockIdx.x * SCAN_B + threadIdx.x;
    if (i <= NN) g_off[i] += g_bsum[blockIdx.x];
    if (i < NN) {
        float d = g_deg[i];
        g_dinv[i] = (d > 0.0f) ? rsqrtf(d) : 0.0f;
    }
}

// ---------------- K5: GEMM1  h1s = (x @ W1^T) * dinv  (3xTF32 tensor core) ----------------
#define BM  128
#define BKg 16
#define AST 20
#define BST 20

__global__ __launch_bounds__(256) void gemm1_tc(const float* __restrict__ X,
                                                const float* __restrict__ W) {
    __shared__ float As[2][BM][AST];
    __shared__ float Bs[2][64][BST];

    const int tid = threadIdx.x;
    const int warp = tid >> 5;
    const int lane = tid & 31;
    const int blockRow = blockIdx.x * BM;

    const int a_row = tid >> 2;           // 0..63 (and +64)
    const int a_c  = (tid & 3) * 4;
    const int b_row = tid >> 2;
    const int b_c  = (tid & 3) * 4;

    const int tig = lane & 3;
    const int g   = lane >> 2;
    const int r0  = (warp << 4) + g;

    float acc[8][4];
#pragma unroll
    for (int j = 0; j < 8; j++)
#pragma unroll
        for (int q = 0; q < 4; q++) acc[j][q] = 0.0f;

    {
        int gr0 = blockRow + a_row;
        int gr1 = blockRow + a_row + 64;
        cp_async16((uint32_t)__cvta_generic_to_shared(&As[0][a_row][a_c]),
                   &X[(size_t)gr0 * FIN + a_c], gr0 < NN ? 16 : 0);
        cp_async16((uint32_t)__cvta_generic_to_shared(&As[0][a_row + 64][a_c]),
                   &X[(size_t)gr1 * FIN + a_c], gr1 < NN ? 16 : 0);
        cp_async16((uint32_t)__cvta_generic_to_shared(&Bs[0][b_row][b_c]),
                   &W[(size_t)b_row * FIN + b_c], 16);
        asm volatile("cp.async.commit_group;");
    }

#pragma unroll 1
    for (int kt = 0; kt < FIN / BKg; kt++) {
        const int st = kt & 1;
        if (kt + 1 < FIN / BKg) {
            const int ns = (kt + 1) & 1;
            const int k0 = (kt + 1) * BKg;
            int gr0 = blockRow + a_row;
            int gr1 = blockRow + a_row + 64;
            cp_async16((uint32_t)__cvta_generic_to_shared(&As[ns][a_row][a_c]),
                       &X[(size_t)gr0 * FIN + k0 + a_c], gr0 < NN ? 16 : 0);
            cp_async16((uint32_t)__cvta_generic_to_shared(&As[ns][a_row + 64][a_c]),
                       &X[(size_t)gr1 * FIN + k0 + a_c], gr1 < NN ? 16 : 0);
            cp_async16((uint32_t)__cvta_generic_to_shared(&Bs[ns][b_row][b_c]),
                       &W[(size_t)b_row * FIN + k0 + b_c], 16);
            asm volatile("cp.async.commit_group;");
            asm volatile("cp.async.wait_group 1;");
        } else {
            asm volatile("cp.async.wait_group 0;");
        }
        __syncthreads();

#pragma unroll
        for (int kk = 0; kk < BKg; kk += 8) {
            float af0 = As[st][r0    ][kk + tig];
            float af1 = As[st][r0 + 8][kk + tig];
            float af2 = As[st][r0    ][kk + tig + 4];
            float af3 = As[st][r0 + 8][kk + tig + 4];
            uint32_t ah[4], al[4];
            ah[0] = cvt_tf32(af0); al[0] = cvt_tf32(af0 - __uint_as_float(ah[0]));
            ah[1] = cvt_tf32(af1); al[1] = cvt_tf32(af1 - __uint_as_float(ah[1]));
            ah[2] = cvt_tf32(af2); al[2] = cvt_tf32(af2 - __uint_as_float(ah[2]));
            ah[3] = cvt_tf32(af3); al[3] = cvt_tf32(af3 - __uint_as_float(ah[3]));
#pragma unroll
            for (int nt = 0; nt < 8; nt++) {
                float bf0 = Bs[st][nt * 8 + g][kk + tig];
                float bf1 = Bs[st][nt * 8 + g][kk + tig + 4];
                uint32_t bh[2], bl[2];
                bh[0] = cvt_tf32(bf0); bl[0] = cvt_tf32(bf0 - __uint_as_float(bh[0]));
                bh[1] = cvt_tf32(bf1); bl[1] = cvt_tf32(bf1 - __uint_as_float(bh[1]));
                mma_tf32(acc[nt], ah, bh);
                mma_tf32(acc[nt], al, bh);
                mma_tf32(acc[nt], ah, bl);
            }
        }
        __syncthreads();
    }

    int grA = blockRow + r0;
    int grB = grA + 8;
    float dA = (grA < NN) ? g_dinv[grA] : 0.0f;
    float dB = (grB < NN) ? g_dinv[grB] : 0.0f;
#pragma unroll
    for (int nt = 0; nt < 8; nt++) {
        int ncol = nt * 8 + 2 * tig;
        if (grA < NN) {
            float2 v = make_float2(acc[nt][0] * dA, acc[nt][1] * dA);
            *(float2*)&g_h1s[(size_t)grA * HID + ncol] = v;
        }
        if (grB < NN) {
            float2 v = make_float2(acc[nt][2] * dB, acc[nt][3] * dB);
            *(float2*)&g_h1s[(size_t)grB * HID + ncol] = v;
        }
    }
}

// ---------------- K6: scatter edges into CSR ----------------
__global__ void scatter_kernel(const int* __restrict__ row, const int* __restrict__ col,
                               const float* __restrict__ ea) {
    int e = blockIdx.x * blockDim.x + threadIdx.x;   // 0..E-1
    int c = col[e];
    int p = g_off[c] + atomicAdd(&g_cur[c], 1);
    g_epack[p] = make_int2(row[e], __float_as_int(ea[e]));
}

// ---------------- K7: layer-1 gather + self-loop + bias + ReLU ----------------
// 16 lanes per node (2 nodes per warp), 4 features per lane via float4
__global__ __launch_bounds__(256) void gather1_kernel(const float* __restrict__ b1) {
    int node = blockIdx.x * 16 + (threadIdx.x >> 4);
    int lane = threadIdx.x & 15;          // feature group: 4 floats each
    if (node >= NN) return;

    int start = g_off[node];
    int end   = g_off[node + 1];
    float acc0 = 0.0f, acc1 = 0.0f, acc2 = 0.0f, acc3 = 0.0f;
#pragma unroll 4
    for (int j = start; j < end; j++) {
        int2 p = __ldg(&g_epack[j]);                 // uniform per 16-lane group
        float w = __int_as_float(p.y);
        float4 v = *(const float4*)&g_h1s[(size_t)p.x * HID + lane * 4];
        acc0 = fmaf(v.x, w, acc0);
        acc1 = fmaf(v.y, w, acc1);
        acc2 = fmaf(v.z, w, acc2);
        acc3 = fmaf(v.w, w, acc3);
    }
    float4 s = *(const float4*)&g_h1s[(size_t)node * HID + lane * 4];
    float di = g_dinv[node];
    float4 bb = *(const float4*)&b1[lane * 4];
    float4 o;
    o.x = fmaxf(fmaf(di, acc0 + s.x, bb.x), 0.0f);
    o.y = fmaxf(fmaf(di, acc1 + s.y, bb.y), 0.0f);
    o.z = fmaxf(fmaf(di, acc2 + s.z, bb.z), 0.0f);
    o.w = fmaxf(fmaf(di, acc3 + s.w, bb.w), 0.0f);
    *(float4*)&g_rel[(size_t)node * HID + lane * 4] = o;
}

// ---------------- K8: GEMM2  zs = (rel @ W2^T) * dinv ----------------
// block = 256 threads = 16 rows x 16 out-cols
__global__ __launch_bounds__(256) void gemm2_kernel(const float* __restrict__ W2) {
    __shared__ float R[16][65];     // [row][k]
    __shared__ float W2s[64][17];   // [k][n]

    const int tid = threadIdx.x;
    const int rowblk = blockIdx.x * 16;

    {
        int n  = tid >> 4;            // 0..15
        int k4 = (tid & 15) << 2;     // 0..60
        float4 w = *(const float4*)&W2[(size_t)n * HID + k4];
        W2s[k4 + 0][n] = w.x;
        W2s[k4 + 1][n] = w.y;
        W2s[k4 + 2][n] = w.z;
        W2s[k4 + 3][n] = w.w;
    }
    {
        int r  = tid >> 4;
        int k4 = (tid & 15) << 2;
        int grow = rowblk + r;
        float4 a = *(const float4*)&g_rel[(size_t)grow * HID + k4];
        R[r][k4 + 0] = a.x;
        R[r][k4 + 1] = a.y;
        R[r][k4 + 2] = a.z;
        R[r][k4 + 3] = a.w;
    }
    __syncthreads();

    int r = tid >> 4;
    int n = tid & 15;
    float acc = 0.0f;
#pragma unroll
    for (int k = 0; k < HID; k++) acc = fmaf(R[r][k], W2s[k][n], acc);
    g_zs[(size_t)(rowblk + r) * CC + n] = acc * g_dinv[rowblk + r];
}

// ---------------- K9: layer-2 gather + self + b2 + log_softmax ----------------
// 16 lanes per node, 2 nodes per warp, 16 nodes per block
__global__ __launch_bounds__(256) void gather2_kernel(float* __restrict__ dout,
                                                      const float* __restrict__ b2) {
    int node = blockIdx.x * 16 + (threadIdx.x >> 4);
    int n = threadIdx.x & 15;

    int start = g_off[node];
    int end   = g_off[node + 1];
    float acc = 0.0f;
#pragma unroll 4
    for (int j = start; j < end; j++) {
        int2 p = __ldg(&g_epack[j]);                 // uniform per 16-lane group
        float w = __int_as_float(p.y);
        acc = fmaf(g_zs[(size_t)p.x * CC + n], w, acc);
    }
    float di = g_dinv[node];
    float v = fmaf(di, acc + g_zs[(size_t)node * CC + n], b2[n]);

    // log-softmax over the 16-lane group
    float m = v;
#pragma unroll
    for (int k = 8; k >= 1; k >>= 1)
        m = fmaxf(m, __shfl_xor_sync(0xFFFFFFFFu, m, k));
    float s = __expf(v - m);
#pragma unroll
    for (int k = 8; k >= 1; k >>= 1)
        s += __shfl_xor_sync(0xFFFFFFFFu, s, k);
    dout[(size_t)node * CC + n] = (v - m) - __logf(s);
}

// ---------------- launch ----------------
extern "C" void kernel_launch(void* const* d_in, const int* in_sizes, int n_in,
                              void* d_out, int out_size) {
    const float* x  = (const float*)d_in[0];
    const int*   ei = (const int*)d_in[1];
    const float* ea = (const float*)d_in[2];
    const float* W1 = (const float*)d_in[3];
    const float* b1 = (const float*)d_in[4];
    const float* W2 = (const float*)d_in[5];
    const float* b2 = (const float*)d_in[6];
    float* dout = (float*)d_out;

    const int* row = ei;        // edge_index[0] (source)
    const int* col = ei + EE;   // edge_index[1] (target)

    init_kernel<<<(NN + 255) / 256, 256>>>();                 // 0
    hist_kernel<<<EE / 256, 256>>>(col, ea);                  // 1
    scanA_kernel<<<NB, SCAN_B>>>();                           // 2
    scanB_kernel<<<1, 32>>>();                                // 3
    scanC_kernel<<<NB, SCAN_B>>>();                           // 4
    gemm1_tc<<<(NN + BM - 1) / BM, 256>>>(x, W1);             // 5  <- ncu -s 5 lands here
    scatter_kernel<<<EE / 256, 256>>>(row, col, ea);          // 6
    gather1_kernel<<<(NN + 15) / 16, 256>>>(b1);              // 7
    gemm2_kernel<<<NN / 16, 256>>>(W2);                       // 8
    gather2_kernel<<<NN / 16, 256>>>(dout, b2);               // 9
}

// round 6
// speedup vs baseline: 1.5236x; 1.1024x over previous
#include <cuda_runtime.h>
#include <math.h>
#include <stdint.h>

// Problem constants (match reference)
#define NN   100000
#define EE   3200000
#define FIN  512
#define HID  64
#define CC   16

#define SCAN_B   1024
#define NB       ((NN + SCAN_B - 1) / SCAN_B)   // 98

// ---------------- device scratch (no allocs allowed) ----------------
__device__ float g_h1s[NN * HID];   // (x @ W1^T) * dinv[row]
__device__ float g_rel[NN * HID];   // relu(layer1 out)
__device__ float g_zs[NN * CC];     // (rel @ W2^T) * dinv[row]
__device__ float g_dinv[NN];
__device__ int   g_cnt[NN];
__device__ int   g_cur[NN];
__device__ int   g_off[NN + 1];
__device__ int   g_bsum[NB];
__device__ int2  g_epack[EE];       // {src row, ew bits} sorted by dst
__device__ uint32_t g_Whi[HID * FIN];  // W1 tf32 hi
__device__ uint32_t g_Wlo[HID * FIN];  // W1 tf32 lo (residual)

__device__ __forceinline__ uint32_t cvt_tf32(float f) {
    uint32_t u;
    asm("cvt.rna.tf32.f32 %0, %1;" : "=r"(u) : "f"(f));
    return u;
}

__device__ __forceinline__ void mma_tf32(float* c, const uint32_t* a, const uint32_t* b) {
    asm volatile(
        "mma.sync.aligned.m16n8k8.row.col.f32.tf32.tf32.f32 "
        "{%0,%1,%2,%3}, {%4,%5,%6,%7}, {%8,%9}, {%0,%1,%2,%3};"
        : "+f"(c[0]), "+f"(c[1]), "+f"(c[2]), "+f"(c[3])
        : "r"(a[0]), "r"(a[1]), "r"(a[2]), "r"(a[3]), "r"(b[0]), "r"(b[1]));
}

__device__ __forceinline__ void cp_async16(uint32_t smem_dst, const void* gsrc, int src_bytes) {
    asm volatile("cp.async.cg.shared.global [%0], [%1], 16, %2;"
                 :: "r"(smem_dst), "l"(gsrc), "r"(src_bytes));
}

// ---------------- K: W pre-convert to tf32 hi/lo ----------------
__global__ void wconv_kernel(const float* __restrict__ W) {
    int i = blockIdx.x * blockDim.x + threadIdx.x;   // 0 .. HID*FIN-1
    float w = W[i];
    uint32_t hi = cvt_tf32(w);
    g_Whi[i] = hi;
    g_Wlo[i] = cvt_tf32(w - __uint_as_float(hi));
}

// ---------------- K0: init (cnt=0, cur=0) ----------------
__global__ void init_kernel() {
    int i = blockIdx.x * blockDim.x + threadIdx.x;
    if (i < NN) {
        g_cnt[i] = 0;
        g_cur[i] = 0;
    }
}

// ---------------- K1: histogram (count only, int atomics) ----------------
__global__ void hist_kernel(const int* __restrict__ col) {
    int e = blockIdx.x * blockDim.x + threadIdx.x;   // 0..E-1
    atomicAdd(&g_cnt[col[e]], 1);
}

// ---------------- K2: scan part A (per-block exclusive scan) ----------------
__global__ __launch_bounds__(SCAN_B) void scanA_kernel() {
    __shared__ int s[SCAN_B];
    int tid = threadIdx.x;
    int i = blockIdx.x * SCAN_B + tid;
    int v = (i < NN) ? g_cnt[i] : 0;
    s[tid] = v;
    __syncthreads();
#pragma unroll
    for (int d = 1; d < SCAN_B; d <<= 1) {
        int t = (tid >= d) ? s[tid - d] : 0;
        __syncthreads();
        s[tid] += t;
        __syncthreads();
    }
    if (i <= NN) g_off[i] = s[tid] - v;   // exclusive
    if (tid == SCAN_B - 1) g_bsum[blockIdx.x] = s[tid];
}

// ---------------- K3: scan part B (parallel scan of the 98 block sums) ----------------
__global__ __launch_bounds__(128) void scanB_kernel() {
    __shared__ int s[128];
    int tid = threadIdx.x;
    int v = (tid < NB) ? g_bsum[tid] : 0;
    s[tid] = v;
    __syncthreads();
#pragma unroll
    for (int d = 1; d < 128; d <<= 1) {
        int t = (tid >= d) ? s[tid - d] : 0;
        __syncthreads();
        s[tid] += t;
        __syncthreads();
    }
    if (tid < NB) g_bsum[tid] = s[tid] - v;   // exclusive
}

// ---------------- K4: scan part C (add block offsets) ----------------
__global__ __launch_bounds__(SCAN_B) void scanC_kernel() {
    int i = blockIdx.x * SCAN_B + threadIdx.x;
    if (i <= NN) g_off[i] += g_bsum[blockIdx.x];
}

// ---------------- K5: scatter edges into CSR ----------------
__global__ void scatter_kernel(const int* __restrict__ row, const int* __restrict__ col,
                               const float* __restrict__ ea) {
    int e = blockIdx.x * blockDim.x + threadIdx.x;   // 0..E-1
    int c = col[e];
    int p = g_off[c] + atomicAdd(&g_cur[c], 1);
    g_epack[p] = make_int2(row[e], __float_as_int(ea[e]));
}

// ---------------- K6: weighted degree from CSR + dinv ----------------
// 4 lanes per node
__global__ __launch_bounds__(256) void degdinv_kernel() {
    int node = blockIdx.x * 64 + (threadIdx.x >> 2);
    int l = threadIdx.x & 3;
    if (node >= NN) return;
    int start = g_off[node];
    int end   = g_off[node + 1];
    float d = 0.0f;
    for (int j = start + l; j < end; j += 4)
        d += __int_as_float(__ldg(&g_epack[j]).y);
    d += __shfl_xor_sync(0xFFFFFFFFu, d, 1);
    d += __shfl_xor_sync(0xFFFFFFFFu, d, 2);
    if (l == 0) {
        d += 1.0f;   // self loop
        g_dinv[node] = (d > 0.0f) ? rsqrtf(d) : 0.0f;
    }
}

// ---------------- K7: GEMM1  h1s = (x @ W1^T) * dinv  (3xTF32, pre-converted B) ----------------
#define BM  128
#define BKg 16
#define AST 20
#define BST 20

__global__ __launch_bounds__(256) void gemm1_tc(const float* __restrict__ X) {
    __shared__ float    As[2][BM][AST];
    __shared__ uint32_t Bh[2][64][BST];
    __shared__ uint32_t Bl[2][64][BST];

    const int tid = threadIdx.x;
    const int warp = tid >> 5;
    const int lane = tid & 31;
    const int blockRow = blockIdx.x * BM;

    const int a_row = tid >> 2;           // 0..63 (and +64)
    const int a_c  = (tid & 3) * 4;
    const int b_row = tid >> 2;
    const int b_c  = (tid & 3) * 4;

    const int tig = lane & 3;
    const int g   = lane >> 2;
    const int r0  = (warp << 4) + g;

    float acc[8][4];
#pragma unroll
    for (int j = 0; j < 8; j++)
#pragma unroll
        for (int q = 0; q < 4; q++) acc[j][q] = 0.0f;

    {
        int gr0 = blockRow + a_row;
        int gr1 = blockRow + a_row + 64;
        cp_async16((uint32_t)__cvta_generic_to_shared(&As[0][a_row][a_c]),
                   &X[(size_t)gr0 * FIN + a_c], gr0 < NN ? 16 : 0);
        cp_async16((uint32_t)__cvta_generic_to_shared(&As[0][a_row + 64][a_c]),
                   &X[(size_t)gr1 * FIN + a_c], gr1 < NN ? 16 : 0);
        cp_async16((uint32_t)__cvta_generic_to_shared(&Bh[0][b_row][b_c]),
                   &g_Whi[(size_t)b_row * FIN + b_c], 16);
        cp_async16((uint32_t)__cvta_generic_to_shared(&Bl[0][b_row][b_c]),
                   &g_Wlo[(size_t)b_row * FIN + b_c], 16);
        asm volatile("cp.async.commit_group;");
    }

#pragma unroll 1
    for (int kt = 0; kt < FIN / BKg; kt++) {
        const int st = kt & 1;
        if (kt + 1 < FIN / BKg) {
            const int ns = (kt + 1) & 1;
            const int k0 = (kt + 1) * BKg;
            int gr0 = blockRow + a_row;
            int gr1 = blockRow + a_row + 64;
            cp_async16((uint32_t)__cvta_generic_to_shared(&As[ns][a_row][a_c]),
                       &X[(size_t)gr0 * FIN + k0 + a_c], gr0 < NN ? 16 : 0);
            cp_async16((uint32_t)__cvta_generic_to_shared(&As[ns][a_row + 64][a_c]),
                       &X[(size_t)gr1 * FIN + k0 + a_c], gr1 < NN ? 16 : 0);
            cp_async16((uint32_t)__cvta_generic_to_shared(&Bh[ns][b_row][b_c]),
                       &g_Whi[(size_t)b_row * FIN + k0 + b_c], 16);
            cp_async16((uint32_t)__cvta_generic_to_shared(&Bl[ns][b_row][b_c]),
                       &g_Wlo[(size_t)b_row * FIN + k0 + b_c], 16);
            asm volatile("cp.async.commit_group;");
            asm volatile("cp.async.wait_group 1;");
        } else {
            asm volatile("cp.async.wait_group 0;");
        }
        __syncthreads();

#pragma unroll
        for (int kk = 0; kk < BKg; kk += 8) {
            float af0 = As[st][r0    ][kk + tig];
            float af1 = As[st][r0 + 8][kk + tig];
            float af2 = As[st][r0    ][kk + tig + 4];
            float af3 = As[st][r0 + 8][kk + tig + 4];
            uint32_t ah[4], al[4];
            ah[0] = cvt_tf32(af0); al[0] = cvt_tf32(af0 - __uint_as_float(ah[0]));
            ah[1] = cvt_tf32(af1); al[1] = cvt_tf32(af1 - __uint_as_float(ah[1]));
            ah[2] = cvt_tf32(af2); al[2] = cvt_tf32(af2 - __uint_as_float(ah[2]));
            ah[3] = cvt_tf32(af3); al[3] = cvt_tf32(af3 - __uint_as_float(ah[3]));
#pragma unroll
            for (int nt = 0; nt < 8; nt++) {
                uint32_t bh[2], bl[2];
                bh[0] = Bh[st][nt * 8 + g][kk + tig];
                bh[1] = Bh[st][nt * 8 + g][kk + tig + 4];
                bl[0] = Bl[st][nt * 8 + g][kk + tig];
                bl[1] = Bl[st][nt * 8 + g][kk + tig + 4];
                mma_tf32(acc[nt], ah, bh);
                mma_tf32(acc[nt], al, bh);
                mma_tf32(acc[nt], ah, bl);
            }
        }
        __syncthreads();
    }

    int grA = blockRow + r0;
    int grB = grA + 8;
    float dA = (grA < NN) ? g_dinv[grA] : 0.0f;
    float dB = (grB < NN) ? g_dinv[grB] : 0.0f;
#pragma unroll
    for (int nt = 0; nt < 8; nt++) {
        int ncol = nt * 8 + 2 * tig;
        if (grA < NN) {
            float2 v = make_float2(acc[nt][0] * dA, acc[nt][1] * dA);
            *(float2*)&g_h1s[(size_t)grA * HID + ncol] = v;
        }
        if (grB < NN) {
            float2 v = make_float2(acc[nt][2] * dB, acc[nt][3] * dB);
            *(float2*)&g_h1s[(size_t)grB * HID + ncol] = v;
        }
    }
}

// ---------------- K8: layer-1 gather + self-loop + bias + ReLU ----------------
// 16 lanes per node (2 nodes per warp), 4 features per lane via float4
__global__ __launch_bounds__(256) void gather1_kernel(const float* __restrict__ b1) {
    int node = blockIdx.x * 16 + (threadIdx.x >> 4);
    int lane = threadIdx.x & 15;          // feature group: 4 floats each
    if (node >= NN) return;

    int start = g_off[node];
    int end   = g_off[node + 1];
    float acc0 = 0.0f, acc1 = 0.0f, acc2 = 0.0f, acc3 = 0.0f;
#pragma unroll 4
    for (int j = start; j < end; j++) {
        int2 p = __ldg(&g_epack[j]);                 // uniform per 16-lane group
        float w = __int_as_float(p.y);
        float4 v = *(const float4*)&g_h1s[(size_t)p.x * HID + lane * 4];
        acc0 = fmaf(v.x, w, acc0);
        acc1 = fmaf(v.y, w, acc1);
        acc2 = fmaf(v.z, w, acc2);
        acc3 = fmaf(v.w, w, acc3);
    }
    float4 s = *(const float4*)&g_h1s[(size_t)node * HID + lane * 4];
    float di = g_dinv[node];
    float4 bb = *(const float4*)&b1[lane * 4];
    float4 o;
    o.x = fmaxf(fmaf(di, acc0 + s.x, bb.x), 0.0f);
    o.y = fmaxf(fmaf(di, acc1 + s.y, bb.y), 0.0f);
    o.z = fmaxf(fmaf(di, acc2 + s.z, bb.z), 0.0f);
    o.w = fmaxf(fmaf(di, acc3 + s.w, bb.w), 0.0f);
    *(float4*)&g_rel[(size_t)node * HID + lane * 4] = o;
}

// ---------------- K9: GEMM2  zs = (rel @ W2^T) * dinv ----------------
__global__ __launch_bounds__(256) void gemm2_kernel(const float* __restrict__ W2) {
    __shared__ float R[16][65];     // [row][k]
    __shared__ float W2s[64][17];   // [k][n]

    const int tid = threadIdx.x;
    const int rowblk = blockIdx.x * 16;

    {
        int n  = tid >> 4;            // 0..15
        int k4 = (tid & 15) << 2;     // 0..60
        float4 w = *(const float4*)&W2[(size_t)n * HID + k4];
        W2s[k4 + 0][n] = w.x;
        W2s[k4 + 1][n] = w.y;
        W2s[k4 + 2][n] = w.z;
        W2s[k4 + 3][n] = w.w;
    }
    {
        int r  = tid >> 4;
        int k4 = (tid & 15) << 2;
        int grow = rowblk + r;
        float4 a = *(const float4*)&g_rel[(size_t)grow * HID + k4];
        R[r][k4 + 0] = a.x;
        R[r][k4 + 1] = a.y;
        R[r][k4 + 2] = a.z;
        R[r][k4 + 3] = a.w;
    }
    __syncthreads();

    int r = tid >> 4;
    int n = tid & 15;
    float acc = 0.0f;
#pragma unroll
    for (int k = 0; k < HID; k++) acc = fmaf(R[r][k], W2s[k][n], acc);
    g_zs[(size_t)(rowblk + r) * CC + n] = acc * g_dinv[rowblk + r];
}

// ---------------- K10: layer-2 gather + self + b2 + log_softmax ----------------
__global__ __launch_bounds__(256) void gather2_kernel(float* __restrict__ dout,
                                                      const float* __restrict__ b2) {
    int node = blockIdx.x * 16 + (threadIdx.x >> 4);
    int n = threadIdx.x & 15;

    int start = g_off[node];
    int end   = g_off[node + 1];
    float acc = 0.0f;
#pragma unroll 4
    for (int j = start; j < end; j++) {
        int2 p = __ldg(&g_epack[j]);                 // uniform per 16-lane group
        float w = __int_as_float(p.y);
        acc = fmaf(g_zs[(size_t)p.x * CC + n], w, acc);
    }
    float di = g_dinv[node];
    float v = fmaf(di, acc + g_zs[(size_t)node * CC + n], b2[n]);

    // log-softmax over the 16-lane group
    float m = v;
#pragma unroll
    for (int k = 8; k >= 1; k >>= 1)
        m = fmaxf(m, __shfl_xor_sync(0xFFFFFFFFu, m, k));
    float s = __expf(v - m);
#pragma unroll
    for (int k = 8; k >= 1; k >>= 1)
        s += __shfl_xor_sync(0xFFFFFFFFu, s, k);
    dout[(size_t)node * CC + n] = (v - m) - __logf(s);
}

// ---------------- launch ----------------
extern "C" void kernel_launch(void* const* d_in, const int* in_sizes, int n_in,
                              void* d_out, int out_size) {
    const float* x  = (const float*)d_in[0];
    const int*   ei = (const int*)d_in[1];
    const float* ea = (const float*)d_in[2];
    const float* W1 = (const float*)d_in[3];
    const float* b1 = (const float*)d_in[4];
    const float* W2 = (const float*)d_in[5];
    const float* b2 = (const float*)d_in[6];
    float* dout = (float*)d_out;

    const int* row = ei;        // edge_index[0] (source)
    const int* col = ei + EE;   // edge_index[1] (target)

    init_kernel<<<(NN + 255) / 256, 256>>>();                 // 0
    wconv_kernel<<<(HID * FIN) / 256, 256>>>(W1);             // 1
    hist_kernel<<<EE / 256, 256>>>(col);                      // 2
    scanA_kernel<<<NB, SCAN_B>>>();                           // 3
    scanB_kernel<<<1, 128>>>();                               // 4
    scanC_kernel<<<NB, SCAN_B>>>();                           // 5
    scatter_kernel<<<EE / 256, 256>>>(row, col, ea);          // 6
    degdinv_kernel<<<(NN + 63) / 64, 256>>>();                // 7
    gemm1_tc<<<(NN + BM - 1) / BM, 256>>>(x);                 // 8
    gather1_kernel<<<(NN + 15) / 16, 256>>>(b1);              // 9
    gemm2_kernel<<<NN / 16, 256>>>(W2);                       // 10
    gather2_kernel<<<NN / 16, 256>>>(dout, b2);               // 11
}